// round 4
// baseline (speedup 1.0000x reference)
#include <cuda_runtime.h>

// out[r,:] = self_tensor[r,:] + sum_{i: sorted_index[i]==r} value[i,:]
// Gather formulation: one warp per output row; binary search locates the
// run of equal indices (sorted_index ascending). D = 128 floats per row,
// one float4 per lane. Index buffer is int32 (JAX x64 off downcasts int64).

#define DCOLS 128

__global__ void gather_add_kernel(const float* __restrict__ self,
                                  const float* __restrict__ value,
                                  const int* __restrict__ index,
                                  float* __restrict__ out,
                                  int M, int N) {
    int warp = (int)((blockIdx.x * (long)blockDim.x + threadIdx.x) >> 5);
    int lane = threadIdx.x & 31;
    if (warp >= N) return;
    const int row = warp;

    // lower_bound(index, index+M, row) — uniform across the warp, broadcast
    // loads; top tree levels stay hot in L1/L2.
    int lo = 0, cnt = M;
    while (cnt > 0) {
        int half = cnt >> 1;
        int mid = lo + half;
        if (__ldg(index + mid) < row) {
            lo = mid + 1;
            cnt -= half + 1;
        } else {
            cnt = half;
        }
    }

    // Start from self row (this fuses the copy), accumulate the run.
    const float4* sp = reinterpret_cast<const float4*>(self)
                       + (long)row * (DCOLS / 4) + lane;
    float4 acc = *sp;

    const float4* vp = reinterpret_cast<const float4*>(value)
                       + (long)lo * (DCOLS / 4) + lane;
    for (int i = lo; i < M && __ldg(index + i) == row; ++i, vp += DCOLS / 4) {
        float4 v = *vp;
        acc.x += v.x; acc.y += v.y; acc.z += v.z; acc.w += v.w;
    }

    reinterpret_cast<float4*>(out)[(long)row * (DCOLS / 4) + lane] = acc;
}

extern "C" void kernel_launch(void* const* d_in, const int* in_sizes, int n_in,
                              void* d_out, int out_size) {
    const float* self_tensor = (const float*)d_in[0];
    const float* value = (const float*)d_in[1];
    const int* sorted_index = (const int*)d_in[2];
    // d_in[3] = pos, unused.
    float* out = (float*)d_out;

    int M = in_sizes[2];                 // scattered rows
    int N = out_size / DCOLS;            // output rows

    const int threads = 256;             // 8 warps -> 8 rows per block
    int blocks = (N + (threads / 32) - 1) / (threads / 32);
    gather_add_kernel<<<blocks, threads>>>(self_tensor, value, sorted_index,
                                           out, M, N);
}

// round 5
// speedup vs baseline: 1.8538x; 1.8538x over previous
#include <cuda_runtime.h>

// out[r,:] = self_tensor[r,:] + sum_{i: sorted_index[i]==r} value[i,:]
// 3-phase gather: (1) zero run-extent scratch, (2) mark run boundaries from
// the sorted index, (3) warp-per-row gather with counted loops (no dependent
// index loads in the hot path). D = 128 floats/row, float4 per lane.
// Index buffer is int32 (JAX x64 off downcasts int64).

#define DCOLS 128
#define N_MAX 262144

__device__ int g_row_lo[N_MAX];
__device__ int g_row_hi[N_MAX];

__global__ void init_bounds_kernel(int N) {
    int t = blockIdx.x * blockDim.x + threadIdx.x;
    if (t < N) { g_row_lo[t] = 0; g_row_hi[t] = 0; }
}

__global__ void mark_bounds_kernel(const int* __restrict__ index, int M) {
    int i = blockIdx.x * blockDim.x + threadIdx.x;
    if (i >= M) return;
    int v = index[i];
    if (i == 0 || index[i - 1] != v) g_row_lo[v] = i;
    if (i == M - 1 || index[i + 1] != v) g_row_hi[v] = i + 1;
}

__global__ void gather_add_kernel(const float* __restrict__ self,
                                  const float* __restrict__ value,
                                  float* __restrict__ out, int N) {
    int warp = (int)((blockIdx.x * (long)blockDim.x + threadIdx.x) >> 5);
    int lane = threadIdx.x & 31;
    if (warp >= N) return;
    const int row = warp;

    int lo = g_row_lo[row];
    int hi = g_row_hi[row];

    // Start from self row (fuses the copy), accumulate the run.
    float4 acc = reinterpret_cast<const float4*>(self)[(long)row * (DCOLS / 4)
                                                       + lane];

    const float4* vp = reinterpret_cast<const float4*>(value)
                       + (long)lo * (DCOLS / 4) + lane;
    for (int i = lo; i < hi; ++i, vp += DCOLS / 4) {
        float4 v = *vp;
        acc.x += v.x; acc.y += v.y; acc.z += v.z; acc.w += v.w;
    }

    reinterpret_cast<float4*>(out)[(long)row * (DCOLS / 4) + lane] = acc;
}

extern "C" void kernel_launch(void* const* d_in, const int* in_sizes, int n_in,
                              void* d_out, int out_size) {
    const float* self_tensor = (const float*)d_in[0];
    const float* value = (const float*)d_in[1];
    const int* sorted_index = (const int*)d_in[2];
    // d_in[3] = pos, unused.
    float* out = (float*)d_out;

    int M = in_sizes[2];                 // scattered rows
    int N = out_size / DCOLS;            // output rows (<= N_MAX)

    init_bounds_kernel<<<(N + 255) / 256, 256>>>(N);
    mark_bounds_kernel<<<(M + 255) / 256, 256>>>(sorted_index, M);

    const int threads = 256;             // 8 warps -> 8 rows per block
    int blocks = (N + (threads / 32) - 1) / (threads / 32);
    gather_add_kernel<<<blocks, threads>>>(self_tensor, value, out, N);
}